// round 6
// baseline (speedup 1.0000x reference)
#include <cuda_runtime.h>
#include <cuda_bf16.h>
#include <cstdint>

// out[i][j] = -sqrt(max(||f_i||^2 + ||f_j||^2 - 2 f_i.f_j, 0)),  f: [8192,512] fp32
// Legacy-MMA path (harness PTX target sm_103 rejects tcgen05).
// bf16 mma.sync m16n8k16 syrk: CTA tile 256x128, warp tile 64x64 (8 warps, 4x2),
// BK=32, 4-stage cp.async pipeline, fused -sqrt epilogue, diagonal forced to 0.

#define NROWS 8192
#define DDIM  512

#define TM 256
#define TN 128
#define BK 32
#define LDSZ 40                    // 32 + 8 bf16 pad -> 80B row stride, conflict-free
#define STAGES 4
#define NKT (DDIM / BK)            // 16

#define A_ELE (TM * LDSZ)          // 10240 bf16 per stage
#define B_ELE (TN * LDSZ)          // 5120
#define SMEM_BYTES (STAGES * (A_ELE + B_ELE) * 2)   // 122880 B

__device__ __nv_bfloat16 g_fb[NROWS * DDIM];
__device__ float g_norms[NROWS];

// ---------------------------------------------------------------------------
// Prep: fp32 -> bf16 copy + exact fp32 squared row norms. One block per row.
// ---------------------------------------------------------------------------
__global__ void prep_kernel(const float* __restrict__ f) {
    const int row = blockIdx.x;
    const float* src = f + (size_t)row * DDIM;
    float s = 0.f;
#pragma unroll
    for (int i = threadIdx.x; i < DDIM; i += 256) {
        float v = src[i];
        s += v * v;
        g_fb[(size_t)row * DDIM + i] = __float2bfloat16(v);
    }
    __shared__ float red[8];
#pragma unroll
    for (int o = 16; o; o >>= 1) s += __shfl_xor_sync(0xffffffffu, s, o);
    if ((threadIdx.x & 31) == 0) red[threadIdx.x >> 5] = s;
    __syncthreads();
    if (threadIdx.x < 8) {
        s = red[threadIdx.x];
#pragma unroll
        for (int o = 4; o; o >>= 1) s += __shfl_xor_sync(0xffu, s, o);
        if (threadIdx.x == 0) g_norms[row] = s;
    }
}

// ---------------------------------------------------------------------------
__global__ __launch_bounds__(256, 1)
void gemm_kernel(float* __restrict__ out) {
    extern __shared__ __nv_bfloat16 sm[];
    __nv_bfloat16* As = sm;                     // [STAGES][TM][LDSZ]
    __nv_bfloat16* Bs = sm + STAGES * A_ELE;    // [STAGES][TN][LDSZ]

    const int tid  = threadIdx.x;
    const int lane = tid & 31;
    const int warp = tid >> 5;
    const int wm = warp >> 1;   // 0..3  -> 64 rows each
    const int wn = warp & 1;    // 0..1  -> 64 cols each

    const int rowA0 = blockIdx.y * TM;
    const int rowB0 = blockIdx.x * TN;

    float acc[4][8][4];
#pragma unroll
    for (int i = 0; i < 4; i++)
#pragma unroll
        for (int j = 0; j < 8; j++)
#pragma unroll
            for (int r = 0; r < 4; r++) acc[i][j][r] = 0.f;

    // issue one K-tile (A: 256x32, B: 128x32 bf16) into stage s_
#define ISSUE(kt_, s_)                                                                       \
    do {                                                                                     \
        const int k0_ = (kt_) * BK;                                                          \
        __nv_bfloat16* as_ = As + (s_) * A_ELE;                                              \
        __nv_bfloat16* bs_ = Bs + (s_) * B_ELE;                                              \
        _Pragma("unroll")                                                                    \
        for (int i_ = 0; i_ < 4; i_++) {                                                     \
            int idx_ = tid + i_ * 256;                                                       \
            int r_   = idx_ >> 2;                                                            \
            int c_   = (idx_ & 3) << 3;                                                      \
            uint32_t d_ = (uint32_t)__cvta_generic_to_shared(as_ + r_ * LDSZ + c_);          \
            const __nv_bfloat16* g_ = g_fb + (size_t)(rowA0 + r_) * DDIM + k0_ + c_;         \
            asm volatile("cp.async.cg.shared.global [%0], [%1], 16;\n" :: "r"(d_), "l"(g_)); \
        }                                                                                    \
        _Pragma("unroll")                                                                    \
        for (int i_ = 0; i_ < 2; i_++) {                                                     \
            int idx_ = tid + i_ * 256;                                                       \
            int r_   = idx_ >> 2;                                                            \
            int c_   = (idx_ & 3) << 3;                                                      \
            uint32_t d_ = (uint32_t)__cvta_generic_to_shared(bs_ + r_ * LDSZ + c_);          \
            const __nv_bfloat16* g_ = g_fb + (size_t)(rowB0 + r_) * DDIM + k0_ + c_;         \
            asm volatile("cp.async.cg.shared.global [%0], [%1], 16;\n" :: "r"(d_), "l"(g_)); \
        }                                                                                    \
        asm volatile("cp.async.commit_group;\n" ::: "memory");                               \
    } while (0)

    ISSUE(0, 0);
    ISSUE(1, 1);
    ISSUE(2, 2);

    for (int kt = 0; kt < NKT; kt++) {
        if (kt < NKT - 2)
            asm volatile("cp.async.wait_group 2;" ::: "memory");
        else if (kt == NKT - 2)
            asm volatile("cp.async.wait_group 1;" ::: "memory");
        else
            asm volatile("cp.async.wait_group 0;" ::: "memory");
        __syncthreads();   // stage kt&3 visible; all warps done with stage (kt-1)&3

        if (kt + 3 < NKT) ISSUE(kt + 3, (kt + 3) & 3);

        const __nv_bfloat16* as = As + (kt & 3) * A_ELE;
        const __nv_bfloat16* bs = Bs + (kt & 3) * B_ELE;

#pragma unroll
        for (int ks = 0; ks < 2; ks++) {   // two k16 steps per BK=32
            uint32_t a[4][4];
            uint32_t b[8][2];
#pragma unroll
            for (int mt = 0; mt < 4; mt++) {
                int row = wm * 64 + mt * 16 + (lane & 7) + ((lane >> 3) & 1) * 8;
                int kk  = ks * 16 + (lane >> 4) * 8;
                uint32_t addr = (uint32_t)__cvta_generic_to_shared(as + row * LDSZ + kk);
                asm volatile(
                    "ldmatrix.sync.aligned.m8n8.x4.shared.b16 {%0,%1,%2,%3}, [%4];\n"
                    : "=r"(a[mt][0]), "=r"(a[mt][1]), "=r"(a[mt][2]), "=r"(a[mt][3])
                    : "r"(addr));
            }
#pragma unroll
            for (int p = 0; p < 4; p++) {
                int row = wn * 64 + p * 16 + (lane & 7) + (lane >> 4) * 8;
                int kk  = ks * 16 + ((lane >> 3) & 1) * 8;
                uint32_t addr = (uint32_t)__cvta_generic_to_shared(bs + row * LDSZ + kk);
                asm volatile(
                    "ldmatrix.sync.aligned.m8n8.x4.shared.b16 {%0,%1,%2,%3}, [%4];\n"
                    : "=r"(b[2 * p][0]), "=r"(b[2 * p][1]),
                      "=r"(b[2 * p + 1][0]), "=r"(b[2 * p + 1][1])
                    : "r"(addr));
            }
#pragma unroll
            for (int mt = 0; mt < 4; mt++) {
#pragma unroll
                for (int nt = 0; nt < 8; nt++) {
                    asm volatile(
                        "mma.sync.aligned.m16n8k16.row.col.f32.bf16.bf16.f32 "
                        "{%0,%1,%2,%3}, {%4,%5,%6,%7}, {%8,%9}, {%0,%1,%2,%3};\n"
                        : "+f"(acc[mt][nt][0]), "+f"(acc[mt][nt][1]),
                          "+f"(acc[mt][nt][2]), "+f"(acc[mt][nt][3])
                        : "r"(a[mt][0]), "r"(a[mt][1]), "r"(a[mt][2]), "r"(a[mt][3]),
                          "r"(b[nt][0]), "r"(b[nt][1]));
                }
            }
        }
    }

    // column norms to SMEM (A-tile smem is free now)
    __syncthreads();
    float* nb_s = reinterpret_cast<float*>(sm);
    if (tid < TN) nb_s[tid] = g_norms[rowB0 + tid];
    __syncthreads();

    // Epilogue: out = -sqrt(max(na + nb - 2g, 0)), diagonal forced to 0.
#pragma unroll
    for (int mt = 0; mt < 4; mt++) {
        int r0 = rowA0 + wm * 64 + mt * 16 + (lane >> 2);
        int r1 = r0 + 8;
        float na0 = g_norms[r0];
        float na1 = g_norms[r1];
#pragma unroll
        for (int nt = 0; nt < 8; nt++) {
            int cl = wn * 64 + nt * 8 + 2 * (lane & 3);
            int c0 = rowB0 + cl;
            int c1 = c0 + 1;
            float nb0 = nb_s[cl];
            float nb1 = nb_s[cl + 1];

            float d00 = fmaxf(na0 + nb0 - 2.f * acc[mt][nt][0], 0.f);
            float d01 = fmaxf(na0 + nb1 - 2.f * acc[mt][nt][1], 0.f);
            float d10 = fmaxf(na1 + nb0 - 2.f * acc[mt][nt][2], 0.f);
            float d11 = fmaxf(na1 + nb1 - 2.f * acc[mt][nt][3], 0.f);

            float v00 = (r0 == c0) ? 0.f : -sqrtf(d00);
            float v01 = (r0 == c1) ? 0.f : -sqrtf(d01);
            float v10 = (r1 == c0) ? 0.f : -sqrtf(d10);
            float v11 = (r1 == c1) ? 0.f : -sqrtf(d11);

            *(float2*)&out[(size_t)r0 * NROWS + c0] = make_float2(v00, v01);
            *(float2*)&out[(size_t)r1 * NROWS + c0] = make_float2(v10, v11);
        }
    }
#undef ISSUE
}

// ---------------------------------------------------------------------------
extern "C" void kernel_launch(void* const* d_in, const int* in_sizes, int n_in,
                              void* d_out, int out_size) {
    const float* f = (const float*)d_in[0];
    float* out = (float*)d_out;
    (void)in_sizes; (void)n_in; (void)out_size;

    cudaFuncSetAttribute(gemm_kernel, cudaFuncAttributeMaxDynamicSharedMemorySize, SMEM_BYTES);

    prep_kernel<<<NROWS, 256>>>(f);
    dim3 grid(NROWS / TN, NROWS / TM);
    gemm_kernel<<<grid, 256, SMEM_BYTES>>>(out);
}

// round 7
// speedup vs baseline: 1.1694x; 1.1694x over previous
#include <cuda_runtime.h>
#include <cuda_bf16.h>
#include <cstdint>

// out[i][j] = -sqrt(max(||f_i||^2 + ||f_j||^2 - 2 f_i.f_j, 0)),  f: [8192,512] fp32
// Legacy-MMA path (harness PTX target sm_103 rejects tcgen05).
// bf16 mma.sync m16n8k16 syrk: CTA tile 128x128, 4 warps (2x2), warp tile 64x64,
// BK=32, 4-stage cp.async pipeline, 2 CTAs/SM, fused -sqrt epilogue, diag = 0.

#define NROWS 8192
#define DDIM  512

#define TM 128
#define TN 128
#define BK 32
#define LDSZ 40                    // 32 + 8 bf16 pad -> 80B row stride, conflict-free
#define STAGES 4
#define NKT (DDIM / BK)            // 16

#define A_ELE (TM * LDSZ)          // 5120 bf16 per stage
#define B_ELE (TN * LDSZ)          // 5120
#define SMEM_BYTES (STAGES * (A_ELE + B_ELE) * 2)   // 81920 B

__device__ __nv_bfloat16 g_fb[NROWS * DDIM];
__device__ float g_norms[NROWS];

// ---------------------------------------------------------------------------
// Prep: fp32 -> bf16 copy + exact fp32 squared row norms. One block per row.
// ---------------------------------------------------------------------------
__global__ void prep_kernel(const float* __restrict__ f) {
    const int row = blockIdx.x;
    const float* src = f + (size_t)row * DDIM;
    float s = 0.f;
#pragma unroll
    for (int i = threadIdx.x; i < DDIM; i += 256) {
        float v = src[i];
        s += v * v;
        g_fb[(size_t)row * DDIM + i] = __float2bfloat16(v);
    }
    __shared__ float red[8];
#pragma unroll
    for (int o = 16; o; o >>= 1) s += __shfl_xor_sync(0xffffffffu, s, o);
    if ((threadIdx.x & 31) == 0) red[threadIdx.x >> 5] = s;
    __syncthreads();
    if (threadIdx.x < 8) {
        s = red[threadIdx.x];
#pragma unroll
        for (int o = 4; o; o >>= 1) s += __shfl_xor_sync(0xffu, s, o);
        if (threadIdx.x == 0) g_norms[row] = s;
    }
}

// ---------------------------------------------------------------------------
__global__ __launch_bounds__(128, 2)
void gemm_kernel(float* __restrict__ out) {
    extern __shared__ __nv_bfloat16 sm[];
    __nv_bfloat16* As = sm;                     // [STAGES][TM][LDSZ]
    __nv_bfloat16* Bs = sm + STAGES * A_ELE;    // [STAGES][TN][LDSZ]

    const int tid  = threadIdx.x;
    const int lane = tid & 31;
    const int warp = tid >> 5;
    const int wm = warp >> 1;   // 0..1 -> 64 rows each
    const int wn = warp & 1;    // 0..1 -> 64 cols each

    const int rowA0 = blockIdx.y * TM;
    const int rowB0 = blockIdx.x * TN;

    float acc[4][8][4];
#pragma unroll
    for (int i = 0; i < 4; i++)
#pragma unroll
        for (int j = 0; j < 8; j++)
#pragma unroll
            for (int r = 0; r < 4; r++) acc[i][j][r] = 0.f;

    // issue one K-tile (A: 128x32, B: 128x32 bf16) into stage s_  (128 threads)
#define ISSUE(kt_, s_)                                                                       \
    do {                                                                                     \
        const int k0_ = (kt_) * BK;                                                          \
        __nv_bfloat16* as_ = As + (s_) * A_ELE;                                              \
        __nv_bfloat16* bs_ = Bs + (s_) * B_ELE;                                              \
        _Pragma("unroll")                                                                    \
        for (int i_ = 0; i_ < 4; i_++) {                                                     \
            int idx_ = tid + i_ * 128;                                                       \
            int r_   = idx_ >> 2;                                                            \
            int c_   = (idx_ & 3) << 3;                                                      \
            uint32_t da_ = (uint32_t)__cvta_generic_to_shared(as_ + r_ * LDSZ + c_);         \
            const __nv_bfloat16* ga_ = g_fb + (size_t)(rowA0 + r_) * DDIM + k0_ + c_;        \
            asm volatile("cp.async.cg.shared.global [%0], [%1], 16;\n" :: "r"(da_), "l"(ga_));\
            uint32_t db_ = (uint32_t)__cvta_generic_to_shared(bs_ + r_ * LDSZ + c_);         \
            const __nv_bfloat16* gb_ = g_fb + (size_t)(rowB0 + r_) * DDIM + k0_ + c_;        \
            asm volatile("cp.async.cg.shared.global [%0], [%1], 16;\n" :: "r"(db_), "l"(gb_));\
        }                                                                                    \
        asm volatile("cp.async.commit_group;\n" ::: "memory");                               \
    } while (0)

    ISSUE(0, 0);
    ISSUE(1, 1);
    ISSUE(2, 2);

    for (int kt = 0; kt < NKT; kt++) {
        if (kt < NKT - 2)
            asm volatile("cp.async.wait_group 2;" ::: "memory");
        else if (kt == NKT - 2)
            asm volatile("cp.async.wait_group 1;" ::: "memory");
        else
            asm volatile("cp.async.wait_group 0;" ::: "memory");
        __syncthreads();   // stage kt&3 visible; all warps done with stage (kt-1)&3

        if (kt + 3 < NKT) ISSUE(kt + 3, (kt + 3) & 3);

        const __nv_bfloat16* as = As + (kt & 3) * A_ELE;
        const __nv_bfloat16* bs = Bs + (kt & 3) * B_ELE;

#pragma unroll
        for (int ks = 0; ks < 2; ks++) {   // two k16 steps per BK=32
            uint32_t a[4][4];
            uint32_t b[8][2];
#pragma unroll
            for (int mt = 0; mt < 4; mt++) {
                int row = wm * 64 + mt * 16 + (lane & 7) + ((lane >> 3) & 1) * 8;
                int kk  = ks * 16 + (lane >> 4) * 8;
                uint32_t addr = (uint32_t)__cvta_generic_to_shared(as + row * LDSZ + kk);
                asm volatile(
                    "ldmatrix.sync.aligned.m8n8.x4.shared.b16 {%0,%1,%2,%3}, [%4];\n"
                    : "=r"(a[mt][0]), "=r"(a[mt][1]), "=r"(a[mt][2]), "=r"(a[mt][3])
                    : "r"(addr));
            }
#pragma unroll
            for (int p = 0; p < 4; p++) {
                int row = wn * 64 + p * 16 + (lane & 7) + (lane >> 4) * 8;
                int kk  = ks * 16 + ((lane >> 3) & 1) * 8;
                uint32_t addr = (uint32_t)__cvta_generic_to_shared(bs + row * LDSZ + kk);
                asm volatile(
                    "ldmatrix.sync.aligned.m8n8.x4.shared.b16 {%0,%1,%2,%3}, [%4];\n"
                    : "=r"(b[2 * p][0]), "=r"(b[2 * p][1]),
                      "=r"(b[2 * p + 1][0]), "=r"(b[2 * p + 1][1])
                    : "r"(addr));
            }
#pragma unroll
            for (int mt = 0; mt < 4; mt++) {
#pragma unroll
                for (int nt = 0; nt < 8; nt++) {
                    asm volatile(
                        "mma.sync.aligned.m16n8k16.row.col.f32.bf16.bf16.f32 "
                        "{%0,%1,%2,%3}, {%4,%5,%6,%7}, {%8,%9}, {%0,%1,%2,%3};\n"
                        : "+f"(acc[mt][nt][0]), "+f"(acc[mt][nt][1]),
                          "+f"(acc[mt][nt][2]), "+f"(acc[mt][nt][3])
                        : "r"(a[mt][0]), "r"(a[mt][1]), "r"(a[mt][2]), "r"(a[mt][3]),
                          "r"(b[nt][0]), "r"(b[nt][1]));
                }
            }
        }
    }

    // column norms to SMEM (tile smem is free now)
    __syncthreads();
    float* nb_s = reinterpret_cast<float*>(sm);
    if (tid < TN) nb_s[tid] = g_norms[rowB0 + tid];
    __syncthreads();

    // Epilogue: out = -sqrt(max(na + nb - 2g, 0)), diagonal forced to 0.
#pragma unroll
    for (int mt = 0; mt < 4; mt++) {
        int r0 = rowA0 + wm * 64 + mt * 16 + (lane >> 2);
        int r1 = r0 + 8;
        float na0 = g_norms[r0];
        float na1 = g_norms[r1];
#pragma unroll
        for (int nt = 0; nt < 8; nt++) {
            int cl = wn * 64 + nt * 8 + 2 * (lane & 3);
            int c0 = rowB0 + cl;
            int c1 = c0 + 1;
            float nb0 = nb_s[cl];
            float nb1 = nb_s[cl + 1];

            float d00 = fmaxf(na0 + nb0 - 2.f * acc[mt][nt][0], 0.f);
            float d01 = fmaxf(na0 + nb1 - 2.f * acc[mt][nt][1], 0.f);
            float d10 = fmaxf(na1 + nb0 - 2.f * acc[mt][nt][2], 0.f);
            float d11 = fmaxf(na1 + nb1 - 2.f * acc[mt][nt][3], 0.f);

            float v00 = (r0 == c0) ? 0.f : -sqrtf(d00);
            float v01 = (r0 == c1) ? 0.f : -sqrtf(d01);
            float v10 = (r1 == c0) ? 0.f : -sqrtf(d10);
            float v11 = (r1 == c1) ? 0.f : -sqrtf(d11);

            *(float2*)&out[(size_t)r0 * NROWS + c0] = make_float2(v00, v01);
            *(float2*)&out[(size_t)r1 * NROWS + c0] = make_float2(v10, v11);
        }
    }
#undef ISSUE
}

// ---------------------------------------------------------------------------
extern "C" void kernel_launch(void* const* d_in, const int* in_sizes, int n_in,
                              void* d_out, int out_size) {
    const float* f = (const float*)d_in[0];
    float* out = (float*)d_out;
    (void)in_sizes; (void)n_in; (void)out_size;

    cudaFuncSetAttribute(gemm_kernel, cudaFuncAttributeMaxDynamicSharedMemorySize, SMEM_BYTES);

    prep_kernel<<<NROWS, 256>>>(f);
    dim3 grid(NROWS / TN, NROWS / TM);
    gemm_kernel<<<grid, 128, SMEM_BYTES>>>(out);
}

// round 8
// speedup vs baseline: 1.2047x; 1.0302x over previous
#include <cuda_runtime.h>
#include <cuda_bf16.h>
#include <cstdint>

// out[i][j] = -sqrt(max(||f_i||^2 + ||f_j||^2 - 2 f_i.f_j, 0)),  f: [8192,512] fp32
// bf16 mma.sync m16n8k16 syrk: CTA tile 128x128, 4 warps (2x2), warp tile 64x64,
// BK=64, 3-stage cp.async pipeline, register double-buffered ldmatrix/mma,
// 2 CTAs/SM, fused -sqrt epilogue, diagonal forced to 0.

#define NROWS 8192
#define DDIM  512

#define TM 128
#define TN 128
#define BK 64
#define LDSZ 72                    // 64 + 8 bf16 pad -> 144B row stride, conflict-free
#define STAGES 3
#define NKT (DDIM / BK)            // 8

#define A_ELE (TM * LDSZ)          // 9216 bf16 per stage
#define B_ELE (TN * LDSZ)          // 9216
#define SMEM_BYTES (STAGES * (A_ELE + B_ELE) * 2)   // 110592 B

__device__ __nv_bfloat16 g_fb[NROWS * DDIM];
__device__ float g_norms[NROWS];

// ---------------------------------------------------------------------------
// Prep: fp32 -> bf16 copy + exact fp32 squared row norms. One block per row.
// ---------------------------------------------------------------------------
__global__ void prep_kernel(const float* __restrict__ f) {
    const int row = blockIdx.x;
    const float* src = f + (size_t)row * DDIM;
    float s = 0.f;
#pragma unroll
    for (int i = threadIdx.x; i < DDIM; i += 256) {
        float v = src[i];
        s += v * v;
        g_fb[(size_t)row * DDIM + i] = __float2bfloat16(v);
    }
    __shared__ float red[8];
#pragma unroll
    for (int o = 16; o; o >>= 1) s += __shfl_xor_sync(0xffffffffu, s, o);
    if ((threadIdx.x & 31) == 0) red[threadIdx.x >> 5] = s;
    __syncthreads();
    if (threadIdx.x < 8) {
        s = red[threadIdx.x];
#pragma unroll
        for (int o = 4; o; o >>= 1) s += __shfl_xor_sync(0xffu, s, o);
        if (threadIdx.x == 0) g_norms[row] = s;
    }
}

// ---------------------------------------------------------------------------
__global__ __launch_bounds__(128, 2)
void gemm_kernel(float* __restrict__ out) {
    extern __shared__ __nv_bfloat16 sm[];
    __nv_bfloat16* As = sm;                     // [STAGES][TM][LDSZ]
    __nv_bfloat16* Bs = sm + STAGES * A_ELE;    // [STAGES][TN][LDSZ]

    const int tid  = threadIdx.x;
    const int lane = tid & 31;
    const int warp = tid >> 5;
    const int wm = warp >> 1;   // 0..1 -> 64 rows each
    const int wn = warp & 1;    // 0..1 -> 64 cols each

    const int rowA0 = blockIdx.y * TM;
    const int rowB0 = blockIdx.x * TN;

    float acc[4][8][4];
#pragma unroll
    for (int i = 0; i < 4; i++)
#pragma unroll
        for (int j = 0; j < 8; j++)
#pragma unroll
            for (int r = 0; r < 4; r++) acc[i][j][r] = 0.f;

    // ldmatrix base offsets (per-thread, constant across tiles)
    const int a_row = wm * 64 + (lane & 7) + ((lane >> 3) & 1) * 8;  // + mt*16
    const int a_kk  = (lane >> 4) * 8;                               // + ks*16
    const int b_row = wn * 64 + (lane & 7) + (lane >> 4) * 8;        // + p*16
    const int b_kk  = ((lane >> 3) & 1) * 8;                         // + ks*16

    // issue one K-tile (A: 128x64, B: 128x64 bf16) into stage s_  (128 threads)
#define ISSUE(kt_, s_)                                                                        \
    do {                                                                                      \
        const int k0_ = (kt_) * BK;                                                           \
        __nv_bfloat16* as_ = As + (s_) * A_ELE;                                               \
        __nv_bfloat16* bs_ = Bs + (s_) * B_ELE;                                               \
        _Pragma("unroll")                                                                     \
        for (int i_ = 0; i_ < 8; i_++) {                                                      \
            int idx_ = tid + i_ * 128;                                                        \
            int r_   = idx_ >> 3;                                                             \
            int c_   = (idx_ & 7) << 3;                                                       \
            uint32_t da_ = (uint32_t)__cvta_generic_to_shared(as_ + r_ * LDSZ + c_);          \
            const __nv_bfloat16* ga_ = g_fb + (size_t)(rowA0 + r_) * DDIM + k0_ + c_;         \
            asm volatile("cp.async.cg.shared.global [%0], [%1], 16;\n" :: "r"(da_), "l"(ga_));\
            uint32_t db_ = (uint32_t)__cvta_generic_to_shared(bs_ + r_ * LDSZ + c_);          \
            const __nv_bfloat16* gb_ = g_fb + (size_t)(rowB0 + r_) * DDIM + k0_ + c_;         \
            asm volatile("cp.async.cg.shared.global [%0], [%1], 16;\n" :: "r"(db_), "l"(gb_));\
        }                                                                                     \
        asm volatile("cp.async.commit_group;\n" ::: "memory");                                \
    } while (0)

    // load one k16 fragment set into register buffer fb_
#define LOAD_FRAGS(as_, bs_, ks_, fb_)                                                        \
    do {                                                                                      \
        _Pragma("unroll")                                                                     \
        for (int mt_ = 0; mt_ < 4; mt_++) {                                                   \
            uint32_t ad_ = (uint32_t)__cvta_generic_to_shared(                                \
                (as_) + (a_row + mt_ * 16) * LDSZ + (ks_) * 16 + a_kk);                       \
            asm volatile(                                                                     \
                "ldmatrix.sync.aligned.m8n8.x4.shared.b16 {%0,%1,%2,%3}, [%4];\n"             \
                : "=r"(a[fb_][mt_][0]), "=r"(a[fb_][mt_][1]),                                 \
                  "=r"(a[fb_][mt_][2]), "=r"(a[fb_][mt_][3])                                  \
                : "r"(ad_));                                                                  \
        }                                                                                     \
        _Pragma("unroll")                                                                     \
        for (int p_ = 0; p_ < 4; p_++) {                                                      \
            uint32_t bd_ = (uint32_t)__cvta_generic_to_shared(                                \
                (bs_) + (b_row + p_ * 16) * LDSZ + (ks_) * 16 + b_kk);                        \
            asm volatile(                                                                     \
                "ldmatrix.sync.aligned.m8n8.x4.shared.b16 {%0,%1,%2,%3}, [%4];\n"             \
                : "=r"(b[fb_][2 * p_][0]), "=r"(b[fb_][2 * p_][1]),                           \
                  "=r"(b[fb_][2 * p_ + 1][0]), "=r"(b[fb_][2 * p_ + 1][1])                    \
                : "r"(bd_));                                                                  \
        }                                                                                     \
    } while (0)

#define MMA_STEP(fb_)                                                                         \
    do {                                                                                      \
        _Pragma("unroll")                                                                     \
        for (int mt_ = 0; mt_ < 4; mt_++) {                                                   \
            _Pragma("unroll")                                                                 \
            for (int nt_ = 0; nt_ < 8; nt_++) {                                               \
                asm volatile(                                                                 \
                    "mma.sync.aligned.m16n8k16.row.col.f32.bf16.bf16.f32 "                    \
                    "{%0,%1,%2,%3}, {%4,%5,%6,%7}, {%8,%9}, {%0,%1,%2,%3};\n"                 \
                    : "+f"(acc[mt_][nt_][0]), "+f"(acc[mt_][nt_][1]),                         \
                      "+f"(acc[mt_][nt_][2]), "+f"(acc[mt_][nt_][3])                          \
                    : "r"(a[fb_][mt_][0]), "r"(a[fb_][mt_][1]),                               \
                      "r"(a[fb_][mt_][2]), "r"(a[fb_][mt_][3]),                               \
                      "r"(b[fb_][nt_][0]), "r"(b[fb_][nt_][1]));                              \
            }                                                                                 \
        }                                                                                     \
    } while (0)

    uint32_t a[2][4][4];
    uint32_t b[2][8][2];

    ISSUE(0, 0);
    ISSUE(1, 1);

    for (int kt = 0; kt < NKT; kt++) {
        if (kt < NKT - 1)
            asm volatile("cp.async.wait_group 1;" ::: "memory");
        else
            asm volatile("cp.async.wait_group 0;" ::: "memory");
        __syncthreads();   // stage kt%3 complete; all warps done reading stage (kt-1)%3

        if (kt + 2 < NKT) ISSUE(kt + 2, (kt + 2) % STAGES);

        const __nv_bfloat16* as = As + (kt % STAGES) * A_ELE;
        const __nv_bfloat16* bs = Bs + (kt % STAGES) * B_ELE;

        // register-pipelined: 4 k16 sub-steps, prefetch ks+1 during MMA(ks)
        LOAD_FRAGS(as, bs, 0, 0);
#pragma unroll
        for (int ks = 0; ks < 4; ks++) {
            if (ks < 3) LOAD_FRAGS(as, bs, ks + 1, (ks + 1) & 1);
            MMA_STEP(ks & 1);
        }
    }

    // column norms to SMEM (tile smem is free now)
    __syncthreads();
    float* nb_s = reinterpret_cast<float*>(sm);
    if (tid < TN) nb_s[tid] = g_norms[rowB0 + tid];
    __syncthreads();

    // Epilogue: out = -sqrt(max(na + nb - 2g, 0)), diagonal forced to 0.
#pragma unroll
    for (int mt = 0; mt < 4; mt++) {
        int r0 = rowA0 + wm * 64 + mt * 16 + (lane >> 2);
        int r1 = r0 + 8;
        float na0 = g_norms[r0];
        float na1 = g_norms[r1];
#pragma unroll
        for (int nt = 0; nt < 8; nt++) {
            int cl = wn * 64 + nt * 8 + 2 * (lane & 3);
            int c0 = rowB0 + cl;
            int c1 = c0 + 1;
            float nb0 = nb_s[cl];
            float nb1 = nb_s[cl + 1];

            float d00 = fmaxf(na0 + nb0 - 2.f * acc[mt][nt][0], 0.f);
            float d01 = fmaxf(na0 + nb1 - 2.f * acc[mt][nt][1], 0.f);
            float d10 = fmaxf(na1 + nb0 - 2.f * acc[mt][nt][2], 0.f);
            float d11 = fmaxf(na1 + nb1 - 2.f * acc[mt][nt][3], 0.f);

            float v00 = (r0 == c0) ? 0.f : -sqrtf(d00);
            float v01 = (r0 == c1) ? 0.f : -sqrtf(d01);
            float v10 = (r1 == c0) ? 0.f : -sqrtf(d10);
            float v11 = (r1 == c1) ? 0.f : -sqrtf(d11);

            *(float2*)&out[(size_t)r0 * NROWS + c0] = make_float2(v00, v01);
            *(float2*)&out[(size_t)r1 * NROWS + c0] = make_float2(v10, v11);
        }
    }
#undef ISSUE
#undef LOAD_FRAGS
#undef MMA_STEP
}

// ---------------------------------------------------------------------------
extern "C" void kernel_launch(void* const* d_in, const int* in_sizes, int n_in,
                              void* d_out, int out_size) {
    const float* f = (const float*)d_in[0];
    float* out = (float*)d_out;
    (void)in_sizes; (void)n_in; (void)out_size;

    cudaFuncSetAttribute(gemm_kernel, cudaFuncAttributeMaxDynamicSharedMemorySize, SMEM_BYTES);

    prep_kernel<<<NROWS, 256>>>(f);
    dim3 grid(NROWS / TN, NROWS / TM);
    gemm_kernel<<<grid, 128, SMEM_BYTES>>>(out);
}

// round 9
// speedup vs baseline: 1.9235x; 1.5967x over previous
#include <cuda_runtime.h>
#include <cuda_bf16.h>
#include <cstdint>

// out[i][j] = -sqrt(max(||f_i||^2 + ||f_j||^2 - 2 f_i.f_j, 0)),  f: [8192,512] fp32
// Symmetric syrk: only upper-triangular CTA tiles computed (2080 of 4096),
// mirror tile written via conflict-free SMEM transpose. bf16 mma.sync m16n8k16,
// CTA tile 128x128, 4 warps (2x2), warp tile 64x64, BK=64, 3-stage cp.async
// pipeline, register double-buffered ldmatrix/mma, 2 CTAs/SM. Diagonal = 0.

#define NROWS 8192
#define DDIM  512

#define TM 128
#define TN 128
#define BK 64
#define LDSZ 72                    // 64 + 8 bf16 pad -> 144B row stride
#define STAGES 3
#define NKT (DDIM / BK)            // 8
#define NT (NROWS / TM)            // 64 tiles per dim
#define NTILES (NT * (NT + 1) / 2) // 2080

#define A_ELE (TM * LDSZ)          // 9216 bf16 per stage
#define B_ELE (TN * LDSZ)
#define PIPE_BYTES (STAGES * (A_ELE + B_ELE) * 2)    // 110592 B
#define STG_S 129                  // staged tile stride (floats): column reads conflict-free
#define EPI_BYTES (TM * STG_S * 4 + TN * 4)          // 66560 B
#define SMEM_BYTES (PIPE_BYTES > EPI_BYTES ? PIPE_BYTES : EPI_BYTES)

__device__ __nv_bfloat16 g_fb[NROWS * DDIM];
__device__ float g_norms[NROWS];

// ---------------------------------------------------------------------------
__global__ void prep_kernel(const float* __restrict__ f) {
    const int row = blockIdx.x;
    const float* src = f + (size_t)row * DDIM;
    float s = 0.f;
#pragma unroll
    for (int i = threadIdx.x; i < DDIM; i += 256) {
        float v = src[i];
        s += v * v;
        g_fb[(size_t)row * DDIM + i] = __float2bfloat16(v);
    }
    __shared__ float red[8];
#pragma unroll
    for (int o = 16; o; o >>= 1) s += __shfl_xor_sync(0xffffffffu, s, o);
    if ((threadIdx.x & 31) == 0) red[threadIdx.x >> 5] = s;
    __syncthreads();
    if (threadIdx.x < 8) {
        s = red[threadIdx.x];
#pragma unroll
        for (int o = 4; o; o >>= 1) s += __shfl_xor_sync(0xffu, s, o);
        if (threadIdx.x == 0) g_norms[row] = s;
    }
}

// ---------------------------------------------------------------------------
__device__ __forceinline__ int tri_offset(int bi) {
    return bi * (2 * NT - bi + 1) / 2;
}

__global__ __launch_bounds__(128, 2)
void gemm_kernel(float* __restrict__ out) {
    extern __shared__ __nv_bfloat16 sm[];
    __nv_bfloat16* As = sm;                     // [STAGES][TM][LDSZ]
    __nv_bfloat16* Bs = sm + STAGES * A_ELE;    // [STAGES][TN][LDSZ]

    const int tid  = threadIdx.x;
    const int lane = tid & 31;
    const int warp = tid >> 5;
    const int wm = warp >> 1;   // 0..1 -> 64 rows each
    const int wn = warp & 1;    // 0..1 -> 64 cols each

    // decode upper-triangular tile index: t -> (bi, bj), bj >= bi
    const int t = blockIdx.x;
    int bi = (int)(((2.f * NT + 1.f) -
                    sqrtf((2.f * NT + 1.f) * (2.f * NT + 1.f) - 8.f * (float)t)) * 0.5f);
    while (bi > 0 && tri_offset(bi) > t) bi--;
    while (tri_offset(bi + 1) <= t) bi++;
    const int bj = bi + (t - tri_offset(bi));

    const int rowA0 = bi * TM;
    const int rowB0 = bj * TN;

    float acc[4][8][4];
#pragma unroll
    for (int i = 0; i < 4; i++)
#pragma unroll
        for (int j = 0; j < 8; j++)
#pragma unroll
            for (int r = 0; r < 4; r++) acc[i][j][r] = 0.f;

    const int a_row = wm * 64 + (lane & 7) + ((lane >> 3) & 1) * 8;  // + mt*16
    const int a_kk  = (lane >> 4) * 8;                               // + ks*16
    const int b_row = wn * 64 + (lane & 7) + (lane >> 4) * 8;        // + p*16
    const int b_kk  = ((lane >> 3) & 1) * 8;                         // + ks*16

#define ISSUE(kt_, s_)                                                                        \
    do {                                                                                      \
        const int k0_ = (kt_) * BK;                                                           \
        __nv_bfloat16* as_ = As + (s_) * A_ELE;                                               \
        __nv_bfloat16* bs_ = Bs + (s_) * B_ELE;                                               \
        _Pragma("unroll")                                                                     \
        for (int i_ = 0; i_ < 8; i_++) {                                                      \
            int idx_ = tid + i_ * 128;                                                        \
            int r_   = idx_ >> 3;                                                             \
            int c_   = (idx_ & 7) << 3;                                                       \
            uint32_t da_ = (uint32_t)__cvta_generic_to_shared(as_ + r_ * LDSZ + c_);          \
            const __nv_bfloat16* ga_ = g_fb + (size_t)(rowA0 + r_) * DDIM + k0_ + c_;         \
            asm volatile("cp.async.cg.shared.global [%0], [%1], 16;\n" :: "r"(da_), "l"(ga_));\
            uint32_t db_ = (uint32_t)__cvta_generic_to_shared(bs_ + r_ * LDSZ + c_);          \
            const __nv_bfloat16* gb_ = g_fb + (size_t)(rowB0 + r_) * DDIM + k0_ + c_;         \
            asm volatile("cp.async.cg.shared.global [%0], [%1], 16;\n" :: "r"(db_), "l"(gb_));\
        }                                                                                     \
        asm volatile("cp.async.commit_group;\n" ::: "memory");                                \
    } while (0)

#define LOAD_FRAGS(as_, bs_, ks_, fb_)                                                        \
    do {                                                                                      \
        _Pragma("unroll")                                                                     \
        for (int mt_ = 0; mt_ < 4; mt_++) {                                                   \
            uint32_t ad_ = (uint32_t)__cvta_generic_to_shared(                                \
                (as_) + (a_row + mt_ * 16) * LDSZ + (ks_) * 16 + a_kk);                       \
            asm volatile(                                                                     \
                "ldmatrix.sync.aligned.m8n8.x4.shared.b16 {%0,%1,%2,%3}, [%4];\n"             \
                : "=r"(a[fb_][mt_][0]), "=r"(a[fb_][mt_][1]),                                 \
                  "=r"(a[fb_][mt_][2]), "=r"(a[fb_][mt_][3])                                  \
                : "r"(ad_));                                                                  \
        }                                                                                     \
        _Pragma("unroll")                                                                     \
        for (int p_ = 0; p_ < 4; p_++) {                                                      \
            uint32_t bd_ = (uint32_t)__cvta_generic_to_shared(                                \
                (bs_) + (b_row + p_ * 16) * LDSZ + (ks_) * 16 + b_kk);                        \
            asm volatile(                                                                     \
                "ldmatrix.sync.aligned.m8n8.x4.shared.b16 {%0,%1,%2,%3}, [%4];\n"             \
                : "=r"(b[fb_][2 * p_][0]), "=r"(b[fb_][2 * p_][1]),                           \
                  "=r"(b[fb_][2 * p_ + 1][0]), "=r"(b[fb_][2 * p_ + 1][1])                    \
                : "r"(bd_));                                                                  \
        }                                                                                     \
    } while (0)

#define MMA_STEP(fb_)                                                                         \
    do {                                                                                      \
        _Pragma("unroll")                                                                     \
        for (int mt_ = 0; mt_ < 4; mt_++) {                                                   \
            _Pragma("unroll")                                                                 \
            for (int nt_ = 0; nt_ < 8; nt_++) {                                               \
                asm volatile(                                                                 \
                    "mma.sync.aligned.m16n8k16.row.col.f32.bf16.bf16.f32 "                    \
                    "{%0,%1,%2,%3}, {%4,%5,%6,%7}, {%8,%9}, {%0,%1,%2,%3};\n"                 \
                    : "+f"(acc[mt_][nt_][0]), "+f"(acc[mt_][nt_][1]),                         \
                      "+f"(acc[mt_][nt_][2]), "+f"(acc[mt_][nt_][3])                          \
                    : "r"(a[fb_][mt_][0]), "r"(a[fb_][mt_][1]),                               \
                      "r"(a[fb_][mt_][2]), "r"(a[fb_][mt_][3]),                               \
                      "r"(b[fb_][nt_][0]), "r"(b[fb_][nt_][1]));                              \
            }                                                                                 \
        }                                                                                     \
    } while (0)

    uint32_t a[2][4][4];
    uint32_t b[2][8][2];

    ISSUE(0, 0);
    ISSUE(1, 1);

    for (int kt = 0; kt < NKT; kt++) {
        if (kt < NKT - 1)
            asm volatile("cp.async.wait_group 1;" ::: "memory");
        else
            asm volatile("cp.async.wait_group 0;" ::: "memory");
        __syncthreads();

        if (kt + 2 < NKT) ISSUE(kt + 2, (kt + 2) % STAGES);

        const __nv_bfloat16* as = As + (kt % STAGES) * A_ELE;
        const __nv_bfloat16* bs = Bs + (kt % STAGES) * B_ELE;

        LOAD_FRAGS(as, bs, 0, 0);
#pragma unroll
        for (int ks = 0; ks < 4; ks++) {
            if (ks < 3) LOAD_FRAGS(as, bs, ks + 1, (ks + 1) & 1);
            MMA_STEP(ks & 1);
        }
    }

    // ---- epilogue: smem now free; staged tile + column norms -------------
    __syncthreads();
    float* staged = reinterpret_cast<float*>(sm);             // [TM][STG_S]
    float* nb_s   = staged + TM * STG_S;                      // [TN]
    if (tid < TN) nb_s[tid] = g_norms[rowB0 + tid];
    __syncthreads();

    // direct store (coalesced) + stage for mirror
#pragma unroll
    for (int mt = 0; mt < 4; mt++) {
        int rl0 = wm * 64 + mt * 16 + (lane >> 2);
        int rl1 = rl0 + 8;
        int r0 = rowA0 + rl0;
        int r1 = rowA0 + rl1;
        float na0 = g_norms[r0];
        float na1 = g_norms[r1];
#pragma unroll
        for (int nt = 0; nt < 8; nt++) {
            int cl = wn * 64 + nt * 8 + 2 * (lane & 3);
            int c0 = rowB0 + cl;
            int c1 = c0 + 1;
            float nb0 = nb_s[cl];
            float nb1 = nb_s[cl + 1];

            float d00 = fmaxf(na0 + nb0 - 2.f * acc[mt][nt][0], 0.f);
            float d01 = fmaxf(na0 + nb1 - 2.f * acc[mt][nt][1], 0.f);
            float d10 = fmaxf(na1 + nb0 - 2.f * acc[mt][nt][2], 0.f);
            float d11 = fmaxf(na1 + nb1 - 2.f * acc[mt][nt][3], 0.f);

            float v00 = (r0 == c0) ? 0.f : -sqrtf(d00);
            float v01 = (r0 == c1) ? 0.f : -sqrtf(d01);
            float v10 = (r1 == c0) ? 0.f : -sqrtf(d10);
            float v11 = (r1 == c1) ? 0.f : -sqrtf(d11);

            *(float2*)&out[(size_t)r0 * NROWS + c0] = make_float2(v00, v01);
            *(float2*)&out[(size_t)r1 * NROWS + c0] = make_float2(v10, v11);

            staged[rl0 * STG_S + cl]     = v00;
            staged[rl0 * STG_S + cl + 1] = v01;
            staged[rl1 * STG_S + cl]     = v10;
            staged[rl1 * STG_S + cl + 1] = v11;
        }
    }

    // mirror tile (skip diagonal blocks): out[rowB0+cl][rowA0+rl] = staged[rl][cl]
    if (bi != bj) {
        __syncthreads();
        // warp w handles cols cl = w*32 .. w*32+31 of the staged tile
#pragma unroll
        for (int i = 0; i < 32; i++) {
            int cl = warp * 32 + i;
            float* orow = out + (size_t)(rowB0 + cl) * NROWS + rowA0;
#pragma unroll
            for (int k = 0; k < 4; k++) {
                int rl = lane + 32 * k;                 // conflict-free: stride 129
                orow[rl] = staged[rl * STG_S + cl];
            }
        }
    }
#undef ISSUE
#undef LOAD_FRAGS
#undef MMA_STEP
}

// ---------------------------------------------------------------------------
extern "C" void kernel_launch(void* const* d_in, const int* in_sizes, int n_in,
                              void* d_out, int out_size) {
    const float* f = (const float*)d_in[0];
    float* out = (float*)d_out;
    (void)in_sizes; (void)n_in; (void)out_size;

    cudaFuncSetAttribute(gemm_kernel, cudaFuncAttributeMaxDynamicSharedMemorySize, SMEM_BYTES);

    prep_kernel<<<NROWS, 256>>>(f);
    gemm_kernel<<<NTILES, 128, SMEM_BYTES>>>(out);
}

// round 10
// speedup vs baseline: 1.9621x; 1.0200x over previous
#include <cuda_runtime.h>
#include <cuda_bf16.h>
#include <cstdint>

// out[i][j] = -sqrt(max(||f_i||^2 + ||f_j||^2 - 2 f_i.f_j, 0)),  f: [8192,512] fp32
// Symmetric syrk: upper-triangular CTA tiles only (2080 of 4096), mirror written
// via transposed SMEM staging with float4 coalesced stores. bf16 mma.sync
// m16n8k16, CTA tile 128x128, 4 warps (2x2), warp tile 64x64, BK=64, 3-stage
// cp.async pipeline, register double-buffered ldmatrix/mma, 2 CTAs/SM. Diag = 0.

#define NROWS 8192
#define DDIM  512

#define TM 128
#define TN 128
#define BK 64
#define LDSZ 72                    // 64 + 8 bf16 pad -> 144B row stride
#define STAGES 3
#define NKT (DDIM / BK)            // 8
#define NT (NROWS / TM)            // 64 tiles per dim
#define NTILES (NT * (NT + 1) / 2) // 2080

#define A_ELE (TM * LDSZ)          // 9216 bf16 per stage
#define B_ELE (TN * LDSZ)
#define PIPE_BYTES (STAGES * (A_ELE + B_ELE) * 2)    // 110592 B
#define STG_S 132                  // transposed-stage stride (floats): 16B-aligned rows,
                                   // conflict-free scatter (bank = 8r+q, distinct)
#define SMEM_BYTES (PIPE_BYTES + TN * 4)             // +512 B persistent col norms

__device__ __nv_bfloat16 g_fb[NROWS * DDIM];
__device__ float g_norms[NROWS];

// ---------------------------------------------------------------------------
// Prep: warp per row. Two passes of 256 floats: float4 loads, coalesced 16B
// bf16 stores. Exact fp32 norms via warp reduction.
// ---------------------------------------------------------------------------
__global__ __launch_bounds__(256)
void prep_kernel(const float* __restrict__ f) {
    const int lane = threadIdx.x & 31;
    const int row  = blockIdx.x * 8 + (threadIdx.x >> 5);
    const float* src = f + (size_t)row * DDIM;
    __nv_bfloat16* dst = g_fb + (size_t)row * DDIM;

    float s = 0.f;
#pragma unroll
    for (int half = 0; half < 2; half++) {
        const float4 v0 = *(const float4*)(src + half * 256 + lane * 8);
        const float4 v1 = *(const float4*)(src + half * 256 + lane * 8 + 4);
        s += v0.x * v0.x + v0.y * v0.y + v0.z * v0.z + v0.w * v0.w;
        s += v1.x * v1.x + v1.y * v1.y + v1.z * v1.z + v1.w * v1.w;
        __nv_bfloat162 p0 = __float22bfloat162_rn(make_float2(v0.x, v0.y));
        __nv_bfloat162 p1 = __float22bfloat162_rn(make_float2(v0.z, v0.w));
        __nv_bfloat162 p2 = __float22bfloat162_rn(make_float2(v1.x, v1.y));
        __nv_bfloat162 p3 = __float22bfloat162_rn(make_float2(v1.z, v1.w));
        uint4 pk;
        pk.x = *(uint32_t*)&p0; pk.y = *(uint32_t*)&p1;
        pk.z = *(uint32_t*)&p2; pk.w = *(uint32_t*)&p3;
        *(uint4*)(dst + half * 256 + lane * 8) = pk;
    }
#pragma unroll
    for (int o = 16; o; o >>= 1) s += __shfl_xor_sync(0xffffffffu, s, o);
    if (lane == 0) g_norms[row] = s;
}

// ---------------------------------------------------------------------------
__device__ __forceinline__ int tri_offset(int bi) {
    return bi * (2 * NT - bi + 1) / 2;
}

__global__ __launch_bounds__(128, 2)
void gemm_kernel(float* __restrict__ out) {
    extern __shared__ __nv_bfloat16 sm[];
    __nv_bfloat16* As = sm;                     // [STAGES][TM][LDSZ]
    __nv_bfloat16* Bs = sm + STAGES * A_ELE;    // [STAGES][TN][LDSZ]
    float* nb_s = reinterpret_cast<float*>(sm + STAGES * (A_ELE + B_ELE)); // [TN] persistent
    float* staged = reinterpret_cast<float*>(sm);       // [TN][STG_S] (reuses pipe region)

    const int tid  = threadIdx.x;
    const int lane = tid & 31;
    const int warp = tid >> 5;
    const int wm = warp >> 1;   // 0..1 -> 64 rows each
    const int wn = warp & 1;    // 0..1 -> 64 cols each

    // decode upper-triangular tile index: t -> (bi, bj), bj >= bi
    const int t = blockIdx.x;
    int bi = (int)(((2.f * NT + 1.f) -
                    sqrtf((2.f * NT + 1.f) * (2.f * NT + 1.f) - 8.f * (float)t)) * 0.5f);
    while (bi > 0 && tri_offset(bi) > t) bi--;
    while (tri_offset(bi + 1) <= t) bi++;
    const int bj = bi + (t - tri_offset(bi));

    const int rowA0 = bi * TM;
    const int rowB0 = bj * TN;

    // persistent column norms (visible to epilogue via mainloop barriers)
    if (tid < TN) nb_s[tid] = g_norms[rowB0 + tid];

    float acc[4][8][4];
#pragma unroll
    for (int i = 0; i < 4; i++)
#pragma unroll
        for (int j = 0; j < 8; j++)
#pragma unroll
            for (int r = 0; r < 4; r++) acc[i][j][r] = 0.f;

    const int a_row = wm * 64 + (lane & 7) + ((lane >> 3) & 1) * 8;  // + mt*16
    const int a_kk  = (lane >> 4) * 8;                               // + ks*16
    const int b_row = wn * 64 + (lane & 7) + (lane >> 4) * 8;        // + p*16
    const int b_kk  = ((lane >> 3) & 1) * 8;                         // + ks*16

#define ISSUE(kt_, s_)                                                                        \
    do {                                                                                      \
        const int k0_ = (kt_) * BK;                                                           \
        __nv_bfloat16* as_ = As + (s_) * A_ELE;                                               \
        __nv_bfloat16* bs_ = Bs + (s_) * B_ELE;                                               \
        _Pragma("unroll")                                                                     \
        for (int i_ = 0; i_ < 8; i_++) {                                                      \
            int idx_ = tid + i_ * 128;                                                        \
            int r_   = idx_ >> 3;                                                             \
            int c_   = (idx_ & 7) << 3;                                                       \
            uint32_t da_ = (uint32_t)__cvta_generic_to_shared(as_ + r_ * LDSZ + c_);          \
            const __nv_bfloat16* ga_ = g_fb + (size_t)(rowA0 + r_) * DDIM + k0_ + c_;         \
            asm volatile("cp.async.cg.shared.global [%0], [%1], 16;\n" :: "r"(da_), "l"(ga_));\
            uint32_t db_ = (uint32_t)__cvta_generic_to_shared(bs_ + r_ * LDSZ + c_);          \
            const __nv_bfloat16* gb_ = g_fb + (size_t)(rowB0 + r_) * DDIM + k0_ + c_;         \
            asm volatile("cp.async.cg.shared.global [%0], [%1], 16;\n" :: "r"(db_), "l"(gb_));\
        }                                                                                     \
        asm volatile("cp.async.commit_group;\n" ::: "memory");                                \
    } while (0)

#define LOAD_FRAGS(as_, bs_, ks_, fb_)                                                        \
    do {                                                                                      \
        _Pragma("unroll")                                                                     \
        for (int mt_ = 0; mt_ < 4; mt_++) {                                                   \
            uint32_t ad_ = (uint32_t)__cvta_generic_to_shared(                                \
                (as_) + (a_row + mt_ * 16) * LDSZ + (ks_) * 16 + a_kk);                       \
            asm volatile(                                                                     \
                "ldmatrix.sync.aligned.m8n8.x4.shared.b16 {%0,%1,%2,%3}, [%4];\n"             \
                : "=r"(a[fb_][mt_][0]), "=r"(a[fb_][mt_][1]),                                 \
                  "=r"(a[fb_][mt_][2]), "=r"(a[fb_][mt_][3])                                  \
                : "r"(ad_));                                                                  \
        }                                                                                     \
        _Pragma("unroll")                                                                     \
        for (int p_ = 0; p_ < 4; p_++) {                                                      \
            uint32_t bd_ = (uint32_t)__cvta_generic_to_shared(                                \
                (bs_) + (b_row + p_ * 16) * LDSZ + (ks_) * 16 + b_kk);                        \
            asm volatile(                                                                     \
                "ldmatrix.sync.aligned.m8n8.x4.shared.b16 {%0,%1,%2,%3}, [%4];\n"             \
                : "=r"(b[fb_][2 * p_][0]), "=r"(b[fb_][2 * p_][1]),                           \
                  "=r"(b[fb_][2 * p_ + 1][0]), "=r"(b[fb_][2 * p_ + 1][1])                    \
                : "r"(bd_));                                                                  \
        }                                                                                     \
    } while (0)

#define MMA_STEP(fb_)                                                                         \
    do {                                                                                      \
        _Pragma("unroll")                                                                     \
        for (int mt_ = 0; mt_ < 4; mt_++) {                                                   \
            _Pragma("unroll")                                                                 \
            for (int nt_ = 0; nt_ < 8; nt_++) {                                               \
                asm volatile(                                                                 \
                    "mma.sync.aligned.m16n8k16.row.col.f32.bf16.bf16.f32 "                    \
                    "{%0,%1,%2,%3}, {%4,%5,%6,%7}, {%8,%9}, {%0,%1,%2,%3};\n"                 \
                    : "+f"(acc[mt_][nt_][0]), "+f"(acc[mt_][nt_][1]),                         \
                      "+f"(acc[mt_][nt_][2]), "+f"(acc[mt_][nt_][3])                          \
                    : "r"(a[fb_][mt_][0]), "r"(a[fb_][mt_][1]),                               \
                      "r"(a[fb_][mt_][2]), "r"(a[fb_][mt_][3]),                               \
                      "r"(b[fb_][nt_][0]), "r"(b[fb_][nt_][1]));                              \
            }                                                                                 \
        }                                                                                     \
    } while (0)

    uint32_t a[2][4][4];
    uint32_t b[2][8][2];

    ISSUE(0, 0);
    ISSUE(1, 1);

    for (int kt = 0; kt < NKT; kt++) {
        if (kt < NKT - 1)
            asm volatile("cp.async.wait_group 1;" ::: "memory");
        else
            asm volatile("cp.async.wait_group 0;" ::: "memory");
        __syncthreads();

        if (kt + 2 < NKT) ISSUE(kt + 2, (kt + 2) % STAGES);

        const __nv_bfloat16* as = As + (kt % STAGES) * A_ELE;
        const __nv_bfloat16* bs = Bs + (kt % STAGES) * B_ELE;

        LOAD_FRAGS(as, bs, 0, 0);
#pragma unroll
        for (int ks = 0; ks < 4; ks++) {
            if (ks < 3) LOAD_FRAGS(as, bs, ks + 1, (ks + 1) & 1);
            MMA_STEP(ks & 1);
        }
    }

    // ---- epilogue ---------------------------------------------------------
    const bool mirror = (bi != bj);
    __syncthreads();   // pipeline smem now reusable as staged[]

#pragma unroll
    for (int mt = 0; mt < 4; mt++) {
        int rl0 = wm * 64 + mt * 16 + (lane >> 2);
        int rl1 = rl0 + 8;
        int r0 = rowA0 + rl0;
        int r1 = rowA0 + rl1;
        float na0 = g_norms[r0];
        float na1 = g_norms[r1];
#pragma unroll
        for (int nt = 0; nt < 8; nt++) {
            int cl = wn * 64 + nt * 8 + 2 * (lane & 3);
            int c0 = rowB0 + cl;
            int c1 = c0 + 1;
            float nb0 = nb_s[cl];
            float nb1 = nb_s[cl + 1];

            float d00 = fmaxf(na0 + nb0 - 2.f * acc[mt][nt][0], 0.f);
            float d01 = fmaxf(na0 + nb1 - 2.f * acc[mt][nt][1], 0.f);
            float d10 = fmaxf(na1 + nb0 - 2.f * acc[mt][nt][2], 0.f);
            float d11 = fmaxf(na1 + nb1 - 2.f * acc[mt][nt][3], 0.f);

            float v00 = (r0 == c0) ? 0.f : -sqrtf(d00);
            float v01 = (r0 == c1) ? 0.f : -sqrtf(d01);
            float v10 = (r1 == c0) ? 0.f : -sqrtf(d10);
            float v11 = (r1 == c1) ? 0.f : -sqrtf(d11);

            *(float2*)&out[(size_t)r0 * NROWS + c0] = make_float2(v00, v01);
            *(float2*)&out[(size_t)r1 * NROWS + c0] = make_float2(v10, v11);

            if (mirror) {  // transposed staging: staged[cl][rl]
                staged[cl * STG_S + rl0]       = v00;
                staged[(cl + 1) * STG_S + rl0] = v01;
                staged[cl * STG_S + rl1]       = v10;
                staged[(cl + 1) * STG_S + rl1] = v11;
            }
        }
    }

    // mirror: out[rowB0+cl][rowA0 + 0..127] = staged[cl][0..127], float4 coalesced
    if (mirror) {
        __syncthreads();
#pragma unroll
        for (int i = 0; i < 32; i++) {
            int cl = warp * 32 + i;
            float4 v = *(float4*)&staged[cl * STG_S + lane * 4];
            *(float4*)(out + (size_t)(rowB0 + cl) * NROWS + rowA0 + lane * 4) = v;
        }
    }
#undef ISSUE
#undef LOAD_FRAGS
#undef MMA_STEP
}

// ---------------------------------------------------------------------------
extern "C" void kernel_launch(void* const* d_in, const int* in_sizes, int n_in,
                              void* d_out, int out_size) {
    const float* f = (const float*)d_in[0];
    float* out = (float*)d_out;
    (void)in_sizes; (void)n_in; (void)out_size;

    cudaFuncSetAttribute(gemm_kernel, cudaFuncAttributeMaxDynamicSharedMemorySize, SMEM_BYTES);

    prep_kernel<<<NROWS / 8, 256>>>(f);
    gemm_kernel<<<NTILES, 128, SMEM_BYTES>>>(out);
}